// round 6
// baseline (speedup 1.0000x reference)
#include <cuda_runtime.h>
#include <cuda_bf16.h>
#include <cstdint>
#include <cstddef>

// ---------------------------------------------------------------------------
// LSTM: B=512, T=512, I=128, H=512, O=128. Gates [g,i,f,o].
// Robust bisection build: conv_w -> reset -> 512x step_kernel (one launch per
// time step; kernel boundary = device-wide sync) -> proj.
// Each step kernel: fused x-GEMM (tf32 mma) + h-GEMM (bf16 mma), c in global.
// All cp.async usage is commit -> wait_group 0 -> syncthreads (no FIFO games).
// ---------------------------------------------------------------------------

// static device scratch (allocation-free rule)
__device__ float          g_wxt[2048 * 128];   // Wx^T [n][k] fp32
__device__ __nv_bfloat16  g_wht[2048 * 512];   // Wh^T [n][k] bf16
__device__ __nv_bfloat16  g_h[2][512 * 512];   // ping-pong h (bf16)
__device__ float          g_c[512 * 512];      // cell state fp32
__device__ float          g_hfinal[512 * 512]; // final h fp32

// ---------------- PTX helpers ----------------------------------------------
__device__ __forceinline__ void cp16(void* dst_smem, const void* src) {
    unsigned s = (unsigned)__cvta_generic_to_shared(dst_smem);
    asm volatile("cp.async.cg.shared.global [%0], [%1], 16;" :: "r"(s), "l"(src) : "memory");
}
__device__ __forceinline__ void cp_commit_wait0() {
    asm volatile("cp.async.commit_group;" ::: "memory");
    asm volatile("cp.async.wait_group 0;" ::: "memory");
}
__device__ __forceinline__ void mma_bf16(float& d0, float& d1, float& d2, float& d3,
                                         unsigned a0, unsigned a1, unsigned a2, unsigned a3,
                                         unsigned b0, unsigned b1) {
    asm volatile(
        "mma.sync.aligned.m16n8k16.row.col.f32.bf16.bf16.f32 "
        "{%0,%1,%2,%3},{%4,%5,%6,%7},{%8,%9},{%0,%1,%2,%3};"
        : "+f"(d0), "+f"(d1), "+f"(d2), "+f"(d3)
        : "r"(a0), "r"(a1), "r"(a2), "r"(a3), "r"(b0), "r"(b1));
}
__device__ __forceinline__ void mma_tf32(float& d0, float& d1, float& d2, float& d3,
                                         unsigned a0, unsigned a1, unsigned a2, unsigned a3,
                                         unsigned b0, unsigned b1) {
    asm volatile(
        "mma.sync.aligned.m16n8k8.row.col.f32.tf32.tf32.f32 "
        "{%0,%1,%2,%3},{%4,%5,%6,%7},{%8,%9},{%0,%1,%2,%3};"
        : "+f"(d0), "+f"(d1), "+f"(d2), "+f"(d3)
        : "r"(a0), "r"(a1), "r"(a2), "r"(a3), "r"(b0), "r"(b1));
}
__device__ __forceinline__ float fsigmoid(float x) { return 1.f / (1.f + __expf(-x)); }
__device__ __forceinline__ float ftanh(float x)    { return 1.f - 2.f / (__expf(2.f * x) + 1.f); }
// clamp: also converts NaN -> finite (fminf/fmaxf return the non-NaN operand)
__device__ __forceinline__ float zclamp(float x)   { return fminf(fmaxf(x, -30.f), 30.f); }

// ---------------- weight transpose / convert --------------------------------
__global__ void conv_w(const float* __restrict__ Wx, const float* __restrict__ Wh) {
    int tid = blockIdx.x * blockDim.x + threadIdx.x;
    int stride = gridDim.x * blockDim.x;
    for (int o = tid; o < 2048 * 128; o += stride) {
        int k = o & 127, n = o >> 7;
        g_wxt[o] = Wx[(size_t)k * 2048 + n];
    }
    for (int o = tid; o < 2048 * 512; o += stride) {
        int k = o & 511, n = o >> 9;
        g_wht[o] = __float2bfloat16(Wh[(size_t)k * 2048 + n]);
    }
}

__global__ void reset_k() {
    int tid = blockIdx.x * blockDim.x + threadIdx.x;
    int stride = gridDim.x * blockDim.x;
    for (int o = tid; o < 512 * 512; o += stride) {
        g_h[0][o] = __float2bfloat16(0.f);
        g_c[o] = 0.f;
    }
}

// ---------------- one LSTM time step (one kernel launch) ---------------------
// grid 128 CTAs x 256 thr. CTA (p,q): p = 128-row batch tile, q = 16 h-cols
// (x4 gates = 64 N cols). smem layout (bytes):
//   Whs [64][520] bf16 : 0      .. 66560
//   Wxs [64][132] f32  : 66560  .. 100352
//   xs  [128][132] f32 : 100352 .. 167936
//   As  [128][136] bf16: 167936 .. 202752
#define STEP_SMEM 202752
__global__ void __launch_bounds__(256, 1) lstm_step(const float* __restrict__ x,
                                                    const float* __restrict__ bias,
                                                    int t) {
    extern __shared__ char smem[];
    __nv_bfloat16* Whs = (__nv_bfloat16*)smem;
    float*         Wxs = (float*)(smem + 66560);
    float*         xs  = (float*)(smem + 100352);
    __nv_bfloat16* As  = (__nv_bfloat16*)(smem + 167936);

    const int tid = threadIdx.x;
    const int lane = tid & 31, warp = tid >> 5;
    const int wm = warp & 3, wn = warp >> 2;
    const int q = blockIdx.x & 31, p = blockIdx.x >> 5;
    const int tr = lane >> 2, tq = lane & 3, tc = tq * 2;
    const int rbase = p * 128;

    const __nv_bfloat16* hsrc = g_h[t & 1];

    // ---- stage Wh slice, Wx slice, x tile (single group, wait 0) ----
    for (int i = tid; i < 4096; i += 256) {          // Whs
        int rowi = i >> 6, ch = i & 63;
        int gate = rowi >> 4, lc = rowi & 15;
        cp16(&Whs[rowi * 520 + ch * 8],
             g_wht + (size_t)(gate * 512 + q * 16 + lc) * 512 + ch * 8);
    }
    for (int i = tid; i < 2048; i += 256) {          // Wxs
        int rowi = i >> 5, ch = i & 31;
        int gate = rowi >> 4, lc = rowi & 15;
        cp16(&Wxs[rowi * 132 + ch * 4],
             g_wxt + (size_t)(gate * 512 + q * 16 + lc) * 128 + ch * 4);
    }
    for (int i = tid; i < 4096; i += 256) {          // xs (x[b][t][:])
        int r = i >> 5, ch = i & 31;
        cp16(&xs[r * 132 + ch * 4],
             x + ((size_t)(rbase + r) * 512 + t) * 128 + ch * 4);
    }
    cp_commit_wait0();
    __syncthreads();

    // ---- acc init: bias ----
    float acc[2][4][4];
    {
        int col = q * 16 + wn * 8 + tc;
#pragma unroll
        for (int g = 0; g < 4; g++) {
            float b0 = bias[g * 512 + col];
            float b1 = bias[g * 512 + col + 1];
#pragma unroll
            for (int im = 0; im < 2; im++) {
                acc[im][g][0] = b0; acc[im][g][1] = b1;
                acc[im][g][2] = b0; acc[im][g][3] = b1;
            }
        }
    }

    // ---- x-GEMM (tf32, K=128) ----
#pragma unroll
    for (int k8 = 0; k8 < 16; k8++) {
        unsigned a[2][4];
        int k = k8 * 8 + tq;
#pragma unroll
        for (int im = 0; im < 2; im++) {
            int r = wm * 32 + im * 16 + tr;
            a[im][0] = __float_as_uint(xs[r * 132 + k]);
            a[im][1] = __float_as_uint(xs[(r + 8) * 132 + k]);
            a[im][2] = __float_as_uint(xs[r * 132 + k + 4]);
            a[im][3] = __float_as_uint(xs[(r + 8) * 132 + k + 4]);
        }
#pragma unroll
        for (int g = 0; g < 4; g++) {
            int n = g * 16 + wn * 8 + tr;
            unsigned b0 = __float_as_uint(Wxs[n * 132 + k]);
            unsigned b1 = __float_as_uint(Wxs[n * 132 + k + 4]);
#pragma unroll
            for (int im = 0; im < 2; im++)
                mma_tf32(acc[im][g][0], acc[im][g][1], acc[im][g][2], acc[im][g][3],
                         a[im][0], a[im][1], a[im][2], a[im][3], b0, b1);
        }
    }

    // ---- h-GEMM: K=512 in 4 chunks, single-buffered, fully synchronous ----
    for (int kc = 0; kc < 4; kc++) {
        __syncthreads();   // previous chunk's reads done before overwrite
        for (int i = tid; i < 2048; i += 256) {
            int r = i >> 4, ch = i & 15;
            cp16(As + r * 136 + ch * 8,
                 hsrc + (size_t)(rbase + r) * 512 + kc * 128 + ch * 8);
        }
        cp_commit_wait0();
        __syncthreads();
#pragma unroll
        for (int k16 = 0; k16 < 8; k16++) {
            unsigned a[2][4];
            int kk = k16 * 16 + tc;
#pragma unroll
            for (int im = 0; im < 2; im++) {
                int r = wm * 32 + im * 16 + tr;
                a[im][0] = *(const unsigned*)(As + r * 136 + kk);
                a[im][1] = *(const unsigned*)(As + (r + 8) * 136 + kk);
                a[im][2] = *(const unsigned*)(As + r * 136 + kk + 8);
                a[im][3] = *(const unsigned*)(As + (r + 8) * 136 + kk + 8);
            }
            int kk2 = kc * 128 + kk;
#pragma unroll
            for (int g = 0; g < 4; g++) {
                int n = g * 16 + wn * 8 + tr;
                unsigned b0 = *(const unsigned*)(Whs + n * 520 + kk2);
                unsigned b1 = *(const unsigned*)(Whs + n * 520 + kk2 + 8);
#pragma unroll
                for (int im = 0; im < 2; im++)
                    mma_bf16(acc[im][g][0], acc[im][g][1], acc[im][g][2], acc[im][g][3],
                             a[im][0], a[im][1], a[im][2], a[im][3], b0, b1);
            }
        }
    }

    // ---- gates + state update (c in global fp32) + h writeback ----
    __nv_bfloat16* hdst = g_h[(t + 1) & 1];
#pragma unroll
    for (int im = 0; im < 2; im++) {
        int grow = rbase + wm * 32 + im * 16 + tr;
        int hcol = q * 16 + wn * 8 + tc;
#pragma unroll
        for (int half = 0; half < 2; half++) {      // half 0: row grow, half 1: grow+8
            int row = grow + half * 8;
            size_t cidx = (size_t)row * 512 + hcol;
            float2 cc = *(float2*)(g_c + cidx);
            float cprev[2] = {cc.x, cc.y};
            float hv[2];
#pragma unroll
            for (int e = 0; e < 2; e++) {
                int ei = half * 2 + e;
                float gv = ftanh(zclamp(acc[im][0][ei]));
                float iv = fsigmoid(zclamp(acc[im][1][ei]));
                float fv = fsigmoid(zclamp(acc[im][2][ei]));
                float ov = fsigmoid(zclamp(acc[im][3][ei]));
                float cn = gv * iv + cprev[e] * fv;
                cprev[e] = cn;
                hv[e] = ftanh(cn) * ov;
            }
            *(float2*)(g_c + cidx) = make_float2(cprev[0], cprev[1]);
            if (t < 511) {
                *(__nv_bfloat162*)(hdst + cidx) = __floats2bfloat162_rn(hv[0], hv[1]);
            } else {
                *(float2*)(g_hfinal + cidx) = make_float2(hv[0], hv[1]);
            }
        }
    }
}

// ---------------- projection + softmax ---------------------------------------
__global__ void proj_kernel(const float* __restrict__ Wp, const float* __restrict__ bp,
                            float* __restrict__ out) {
    __shared__ float hs[512];
    __shared__ float wred[8];
    int b = blockIdx.x, o = threadIdx.x;
    for (int i = o; i < 512; i += 128)
        hs[i] = fminf(fmaxf(g_hfinal[(size_t)b * 512 + i], -1.f), 1.f);
    __syncthreads();
    float acc = bp[o];
#pragma unroll 8
    for (int k = 0; k < 512; k++) acc = fmaf(hs[k], Wp[(size_t)k * 128 + o], acc);
    float m = acc;
#pragma unroll
    for (int s = 16; s > 0; s >>= 1) m = fmaxf(m, __shfl_xor_sync(0xffffffffu, m, s));
    int w = o >> 5, ln = o & 31;
    if (ln == 0) wred[w] = m;
    __syncthreads();
    m = fmaxf(fmaxf(wred[0], wred[1]), fmaxf(wred[2], wred[3]));
    float e = __expf(acc - m);
    float s = e;
#pragma unroll
    for (int sh = 16; sh > 0; sh >>= 1) s += __shfl_xor_sync(0xffffffffu, s, sh);
    if (ln == 0) wred[4 + w] = s;
    __syncthreads();
    s = wred[4] + wred[5] + wred[6] + wred[7];
    out[(size_t)b * 128 + o] = e / s;
}

// ---------------- launch ------------------------------------------------------
// Inputs resolved BY ELEMENT COUNT (all six sizes distinct):
//   x: 33554432, Wx: 262144, Wh: 1048576, b: 2048, Wp: 65536, bp: 128
extern "C" void kernel_launch(void* const* d_in, const int* in_sizes, int n_in,
                              void* d_out, int out_size) {
    (void)out_size;
    const float *x = 0, *Wx = 0, *Wh = 0, *b = 0, *Wp = 0, *bp = 0;
    for (int i = 0; i < n_in; i++) {
        switch (in_sizes[i]) {
            case 512 * 512 * 128: x  = (const float*)d_in[i]; break;
            case 128 * 2048:      Wx = (const float*)d_in[i]; break;
            case 512 * 2048:      Wh = (const float*)d_in[i]; break;
            case 2048:            b  = (const float*)d_in[i]; break;
            case 512 * 128:       Wp = (const float*)d_in[i]; break;
            case 128:             bp = (const float*)d_in[i]; break;
            default: break;
        }
    }
    float* out = (float*)d_out;

    cudaFuncSetAttribute(lstm_step, cudaFuncAttributeMaxDynamicSharedMemorySize, STEP_SMEM);

    conv_w<<<512, 256>>>(Wx, Wh);
    reset_k<<<128, 256>>>();
    for (int t = 0; t < 512; t++)
        lstm_step<<<128, 256, STEP_SMEM>>>(x, b, t);
    proj_kernel<<<512, 128>>>(Wp, bp, out);
}

// round 7
// speedup vs baseline: 1.4396x; 1.4396x over previous
#include <cuda_runtime.h>
#include <cuda_bf16.h>
#include <cstdint>
#include <cstddef>

// ---------------------------------------------------------------------------
// LSTM: B=512, T=512, I=128, H=512, O=128. Gates [g,i,f,o].
// conv_w/conv_x -> reset -> lstm_rec (persistent 128 CTAs, resident weights,
// bf16 mma for x-GEMM and h-GEMM, double-buffered h, grid barrier per step)
// -> proj (softmax).
// Round-7: fixes round-4's smem layout bug (As double-buffer region was sized
// for ONE buffer; buffer 1 aliased xs -> deterministic NaN).
// ---------------------------------------------------------------------------

#define NCTA 128

// static device scratch (allocation-free rule)
__device__ __nv_bfloat16  g_wxtb[2048 * 128];        // Wx^T [n][k] bf16
__device__ __nv_bfloat16  g_wht[2048 * 512];         // Wh^T [n][k] bf16
__device__ __nv_bfloat16  g_xb[(size_t)512 * 512 * 128]; // x as bf16 [b][t][i]
__device__ __nv_bfloat16  g_h[2][512 * 512];         // ping-pong h (bf16)
__device__ float          g_hfinal[512 * 512];       // final h fp32
__device__ unsigned       g_barr[32 * 32];           // split barrier counters

// ---------------- PTX helpers ----------------------------------------------
__device__ __forceinline__ void cp16(void* dst_smem, const void* src) {
    unsigned s = (unsigned)__cvta_generic_to_shared(dst_smem);
    asm volatile("cp.async.cg.shared.global [%0], [%1], 16;" :: "r"(s), "l"(src) : "memory");
}
__device__ __forceinline__ void cp_commit() {
    asm volatile("cp.async.commit_group;" ::: "memory");
}
template <int N>
__device__ __forceinline__ void cp_wait() {
    asm volatile("cp.async.wait_group %0;" :: "n"(N) : "memory");
}
__device__ __forceinline__ void mma_bf16(float& d0, float& d1, float& d2, float& d3,
                                         unsigned a0, unsigned a1, unsigned a2, unsigned a3,
                                         unsigned b0, unsigned b1) {
    asm volatile(
        "mma.sync.aligned.m16n8k16.row.col.f32.bf16.bf16.f32 "
        "{%0,%1,%2,%3},{%4,%5,%6,%7},{%8,%9},{%0,%1,%2,%3};"
        : "+f"(d0), "+f"(d1), "+f"(d2), "+f"(d3)
        : "r"(a0), "r"(a1), "r"(a2), "r"(a3), "r"(b0), "r"(b1));
}
__device__ __forceinline__ float fsigmoid(float x) { return 1.f / (1.f + __expf(-x)); }
__device__ __forceinline__ float ftanh(float x)    { return 1.f - 2.f / (__expf(2.f * x) + 1.f); }
__device__ __forceinline__ float zclamp(float x)   { return fminf(fmaxf(x, -30.f), 30.f); }

// ---------------- converts ---------------------------------------------------
__global__ void conv_w(const float* __restrict__ Wx, const float* __restrict__ Wh) {
    int tid = blockIdx.x * blockDim.x + threadIdx.x;
    int stride = gridDim.x * blockDim.x;
    for (int o = tid; o < 2048 * 128; o += stride) {
        int k = o & 127, n = o >> 7;
        g_wxtb[o] = __float2bfloat16(Wx[(size_t)k * 2048 + n]);
    }
    for (int o = tid; o < 2048 * 512; o += stride) {
        int k = o & 511, n = o >> 9;
        g_wht[o] = __float2bfloat16(Wh[(size_t)k * 2048 + n]);
    }
}

__global__ void conv_x(const float* __restrict__ x) {
    size_t N = (size_t)512 * 512 * 128;
    for (size_t o = (size_t)blockIdx.x * blockDim.x + threadIdx.x; o < N;
         o += (size_t)gridDim.x * blockDim.x)
        g_xb[o] = __float2bfloat16(x[o]);
}

__global__ void reset_k() {
    int tid = blockIdx.x * blockDim.x + threadIdx.x;
    if (tid < 32 * 32) g_barr[tid] = 0u;
    for (int o = tid; o < 512 * 512; o += gridDim.x * blockDim.x)
        g_h[0][o] = __float2bfloat16(0.f);
}

// ---------------- persistent recurrence --------------------------------------
// CTA (p,q): p = 128-row batch tile, q = 16 h-cols (x4 gates = 64 N cols).
// smem layout (bytes) — all buffer sizes honest this time:
//   Whs [64][520] bf16 : 0      .. 66560   (66560)
//   Wxs [64][136] bf16 : 66560  .. 83968   (17408)
//   As  2x[128][136] bf16 : 83968 .. 153600 (2 x 34816 = 69632)
//   xs  [128][136] bf16 : 153600 .. 188416 (34816)
#define AS_ELEMS (128 * 136)        // one As buffer, in bf16 ELEMENTS
#define REC_SMEM 188416
__global__ void __launch_bounds__(256, 1) lstm_rec(const float* __restrict__ bias) {
    extern __shared__ char smem[];
    __nv_bfloat16* Whs = (__nv_bfloat16*)smem;
    __nv_bfloat16* Wxs = (__nv_bfloat16*)(smem + 66560);
    __nv_bfloat16* As0 = (__nv_bfloat16*)(smem + 83968);
    __nv_bfloat16* xs  = (__nv_bfloat16*)(smem + 153600);

    const int tid = threadIdx.x;
    const int lane = tid & 31, warp = tid >> 5;
    const int wm = warp & 3, wn = warp >> 2;
    const int q = blockIdx.x & 31, p = blockIdx.x >> 5;
    const int tr = lane >> 2, tc = (lane & 3) * 2;
    const int rbase = p * 128;

    // ---- prologue: resident Whs, Wxs; xs for t=0 ----
    for (int i = tid; i < 4096; i += 256) {          // Whs: 64 rows x 64 chunks
        int rowi = i >> 6, ch = i & 63;
        int gate = rowi >> 4, lc = rowi & 15;
        cp16(&Whs[rowi * 520 + ch * 8],
             g_wht + (size_t)(gate * 512 + q * 16 + lc) * 512 + ch * 8);
    }
    for (int i = tid; i < 1024; i += 256) {          // Wxs: 64 rows x 16 chunks
        int rowi = i >> 4, ch = i & 15;
        int gate = rowi >> 4, lc = rowi & 15;
        cp16(&Wxs[rowi * 136 + ch * 8],
             g_wxtb + (size_t)(gate * 512 + q * 16 + lc) * 128 + ch * 8);
    }
    for (int i = tid; i < 2048; i += 256) {          // xs: 128 rows x 16 chunks
        int r = i >> 4, ch = i & 15;
        cp16(&xs[r * 136 + ch * 8],
             g_xb + ((size_t)(rbase + r) * 512 + 0) * 128 + ch * 8);
    }
    cp_commit(); cp_wait<0>(); __syncthreads();

    // bias per thread (constant over steps)
    float bz[4][2];
    {
        int col = q * 16 + wn * 8 + tc;
#pragma unroll
        for (int g = 0; g < 4; g++) {
            bz[g][0] = bias[g * 512 + col];
            bz[g][1] = bias[g * 512 + col + 1];
        }
    }

    float c[2][4];
#pragma unroll
    for (int im = 0; im < 2; im++)
#pragma unroll
        for (int e = 0; e < 4; e++) c[im][e] = 0.f;

    for (int t = 0; t < 512; ++t) {
        const int cur = t & 1, nxt = cur ^ 1;
        const __nv_bfloat16* hsrc = g_h[cur];

        // issue h chunk 0 into As buffer 0
        for (int i = tid; i < 2048; i += 256) {
            int r = i >> 4, ch = i & 15;
            cp16(As0 + r * 136 + ch * 8, hsrc + (size_t)(rbase + r) * 512 + ch * 8);
        }
        cp_commit();   // pending: {h0}

        // ---- x-GEMM (bf16, K=128) ----
        float acc[2][4][4];
#pragma unroll
        for (int im = 0; im < 2; im++)
#pragma unroll
            for (int g = 0; g < 4; g++) {
                acc[im][g][0] = bz[g][0]; acc[im][g][1] = bz[g][1];
                acc[im][g][2] = bz[g][0]; acc[im][g][3] = bz[g][1];
            }
#pragma unroll
        for (int k16 = 0; k16 < 8; k16++) {
            unsigned a[2][4];
            int kk = k16 * 16 + tc;
#pragma unroll
            for (int im = 0; im < 2; im++) {
                int r = wm * 32 + im * 16 + tr;
                a[im][0] = *(const unsigned*)(xs + r * 136 + kk);
                a[im][1] = *(const unsigned*)(xs + (r + 8) * 136 + kk);
                a[im][2] = *(const unsigned*)(xs + r * 136 + kk + 8);
                a[im][3] = *(const unsigned*)(xs + (r + 8) * 136 + kk + 8);
            }
#pragma unroll
            for (int g = 0; g < 4; g++) {
                int n = g * 16 + wn * 8 + tr;
                unsigned b0 = *(const unsigned*)(Wxs + n * 136 + kk);
                unsigned b1 = *(const unsigned*)(Wxs + n * 136 + kk + 8);
#pragma unroll
                for (int im = 0; im < 2; im++)
                    mma_bf16(acc[im][g][0], acc[im][g][1], acc[im][g][2], acc[im][g][3],
                             a[im][0], a[im][1], a[im][2], a[im][3], b0, b1);
            }
        }
        __syncthreads();   // xs reads done before the t+1 prefetch overwrites it

        // ---- h-GEMM: K=512 in 4 chunks, double-buffered ----
        for (int kc = 0; kc < 4; kc++) {
            if (kc < 3) {
                // issue next chunk into the other buffer
                __nv_bfloat16* dst = As0 + ((kc + 1) & 1) * AS_ELEMS;
                for (int i = tid; i < 2048; i += 256) {
                    int r = i >> 4, ch = i & 15;
                    cp16(dst + r * 136 + ch * 8,
                         hsrc + (size_t)(rbase + r) * 512 + (kc + 1) * 128 + ch * 8);
                }
                cp_commit();
                if (kc == 2 && t < 511) {   // prefetch x tile for t+1
                    for (int i = tid; i < 2048; i += 256) {
                        int r = i >> 4, ch = i & 15;
                        cp16(&xs[r * 136 + ch * 8],
                             g_xb + ((size_t)(rbase + r) * 512 + (t + 1)) * 128 + ch * 8);
                    }
                    cp_commit();
                    cp_wait<2>();           // drains h2; {h3, x'} pending
                } else {
                    cp_wait<1>();           // drains h(kc); next chunk pending
                }
            } else {
                // kc==3: pending {h3,x'} if t<511 else {h3}
                if (t < 511) cp_wait<1>(); else cp_wait<0>();
            }
            __syncthreads();
            const __nv_bfloat16* As = As0 + (kc & 1) * AS_ELEMS;
#pragma unroll
            for (int k16 = 0; k16 < 8; k16++) {
                unsigned a[2][4];
                int kk = k16 * 16 + tc;
#pragma unroll
                for (int im = 0; im < 2; im++) {
                    int r = wm * 32 + im * 16 + tr;
                    a[im][0] = *(const unsigned*)(As + r * 136 + kk);
                    a[im][1] = *(const unsigned*)(As + (r + 8) * 136 + kk);
                    a[im][2] = *(const unsigned*)(As + r * 136 + kk + 8);
                    a[im][3] = *(const unsigned*)(As + (r + 8) * 136 + kk + 8);
                }
                int kk2 = kc * 128 + kk;
#pragma unroll
                for (int g = 0; g < 4; g++) {
                    int n = g * 16 + wn * 8 + tr;
                    unsigned b0 = *(const unsigned*)(Whs + n * 520 + kk2);
                    unsigned b1 = *(const unsigned*)(Whs + n * 520 + kk2 + 8);
#pragma unroll
                    for (int im = 0; im < 2; im++)
                        mma_bf16(acc[im][g][0], acc[im][g][1], acc[im][g][2], acc[im][g][3],
                                 a[im][0], a[im][1], a[im][2], a[im][3], b0, b1);
                }
            }
            __syncthreads();   // all reads of this buffer done before next overwrite
        }

        // ---- gates + state update + h writeback ----
#pragma unroll
        for (int im = 0; im < 2; im++) {
            int grow = rbase + wm * 32 + im * 16 + tr;
            int hcol = q * 16 + wn * 8 + tc;
            float hv[4];
#pragma unroll
            for (int e = 0; e < 4; e++) {
                float gv = ftanh(zclamp(acc[im][0][e]));
                float iv = fsigmoid(zclamp(acc[im][1][e]));
                float fv = fsigmoid(zclamp(acc[im][2][e]));
                float ov = fsigmoid(zclamp(acc[im][3][e]));
                float cc = gv * iv + c[im][e] * fv;
                c[im][e] = cc;
                hv[e] = ftanh(cc) * ov;
            }
            if (t < 511) {
                *(__nv_bfloat162*)(g_h[nxt] + (size_t)grow * 512 + hcol) =
                    __floats2bfloat162_rn(hv[0], hv[1]);
                *(__nv_bfloat162*)(g_h[nxt] + (size_t)(grow + 8) * 512 + hcol) =
                    __floats2bfloat162_rn(hv[2], hv[3]);
            } else {
                *(float2*)(g_hfinal + (size_t)grow * 512 + hcol) = make_float2(hv[0], hv[1]);
                *(float2*)(g_hfinal + (size_t)(grow + 8) * 512 + hcol) = make_float2(hv[2], hv[3]);
            }
        }

        if (t == 511) break;

        // ---- grid barrier: split counters, warp-0 poll ----
        __threadfence();
        __syncthreads();
        if (warp == 0) {
            if (lane == 0) atomicAdd(&g_barr[(blockIdx.x & 31) << 5], 1u);
            unsigned target = (unsigned)(t + 1) * NCTA;
            for (;;) {
                unsigned v = *(volatile unsigned*)&g_barr[lane << 5];
#pragma unroll
                for (int s = 16; s > 0; s >>= 1)
                    v += __shfl_xor_sync(0xffffffffu, v, s);
                if (v >= target) break;
            }
            __threadfence();
        }
        __syncthreads();
        cp_wait<0>();     // x' (only remaining pending group) now complete
        __syncthreads();
    }
}

// ---------------- projection + softmax ---------------------------------------
__global__ void proj_kernel(const float* __restrict__ Wp, const float* __restrict__ bp,
                            float* __restrict__ out) {
    __shared__ float hs[512];
    __shared__ float wred[8];
    int b = blockIdx.x, o = threadIdx.x;
    for (int i = o; i < 512; i += 128)
        hs[i] = fminf(fmaxf(g_hfinal[(size_t)b * 512 + i], -1.f), 1.f);
    __syncthreads();
    float acc = bp[o];
#pragma unroll 8
    for (int k = 0; k < 512; k++) acc = fmaf(hs[k], Wp[(size_t)k * 128 + o], acc);
    float m = acc;
#pragma unroll
    for (int s = 16; s > 0; s >>= 1) m = fmaxf(m, __shfl_xor_sync(0xffffffffu, m, s));
    int w = o >> 5, ln = o & 31;
    if (ln == 0) wred[w] = m;
    __syncthreads();
    m = fmaxf(fmaxf(wred[0], wred[1]), fmaxf(wred[2], wred[3]));
    float e = __expf(acc - m);
    float s = e;
#pragma unroll
    for (int sh = 16; sh > 0; sh >>= 1) s += __shfl_xor_sync(0xffffffffu, s, sh);
    if (ln == 0) wred[4 + w] = s;
    __syncthreads();
    s = wred[4] + wred[5] + wred[6] + wred[7];
    out[(size_t)b * 128 + o] = e / s;
}

// ---------------- launch ------------------------------------------------------
// Inputs resolved BY ELEMENT COUNT (all six sizes distinct):
//   x: 33554432, Wx: 262144, Wh: 1048576, b: 2048, Wp: 65536, bp: 128
extern "C" void kernel_launch(void* const* d_in, const int* in_sizes, int n_in,
                              void* d_out, int out_size) {
    (void)out_size;
    const float *x = 0, *Wx = 0, *Wh = 0, *b = 0, *Wp = 0, *bp = 0;
    for (int i = 0; i < n_in; i++) {
        switch (in_sizes[i]) {
            case 512 * 512 * 128: x  = (const float*)d_in[i]; break;
            case 128 * 2048:      Wx = (const float*)d_in[i]; break;
            case 512 * 2048:      Wh = (const float*)d_in[i]; break;
            case 2048:            b  = (const float*)d_in[i]; break;
            case 512 * 128:       Wp = (const float*)d_in[i]; break;
            case 128:             bp = (const float*)d_in[i]; break;
            default: break;
        }
    }
    float* out = (float*)d_out;

    cudaFuncSetAttribute(lstm_rec, cudaFuncAttributeMaxDynamicSharedMemorySize, REC_SMEM);

    conv_w<<<512, 256>>>(Wx, Wh);
    conv_x<<<512, 256>>>(x);
    reset_k<<<128, 256>>>();
    lstm_rec<<<NCTA, 256, REC_SMEM>>>(b);
    proj_kernel<<<512, 128>>>(Wp, bp, out);
}

// round 8
// speedup vs baseline: 1.9980x; 1.3879x over previous
#include <cuda_runtime.h>
#include <cuda_bf16.h>
#include <cstdint>
#include <cstddef>

// ---------------------------------------------------------------------------
// LSTM: B=512, T=512, I=128, H=512, O=128. Gates [g,i,f,o].
// Persistent 128 CTAs. CTA (p,q): p = 128-row batch tile (4 groups),
// q = 16 h-cols x 4 gates = 64 N cols. Weights smem-resident.
// Round-8: per-p barriers (32 CTAs), x-GEMM in barrier shadow, triple-buffered
// h pipeline, MUFU-only gate math.
// ---------------------------------------------------------------------------

#define NCTA 128

__device__ __nv_bfloat16  g_wxtb[2048 * 128];            // Wx^T [n][k] bf16
__device__ __nv_bfloat16  g_wht[2048 * 512];             // Wh^T [n][k] bf16
__device__ __nv_bfloat16  g_xb[(size_t)512 * 512 * 128]; // x bf16 [b][t][i]
__device__ __nv_bfloat16  g_h[2][512 * 512];             // ping-pong h
__device__ float          g_hfinal[512 * 512];           // final h fp32
__device__ unsigned       g_barr[32 * 32];               // per-p counters @ [p*32]

// ---------------- PTX helpers ----------------------------------------------
__device__ __forceinline__ void cp16(void* dst_smem, const void* src) {
    unsigned s = (unsigned)__cvta_generic_to_shared(dst_smem);
    asm volatile("cp.async.cg.shared.global [%0], [%1], 16;" :: "r"(s), "l"(src) : "memory");
}
__device__ __forceinline__ void cp_commit() {
    asm volatile("cp.async.commit_group;" ::: "memory");
}
template <int N>
__device__ __forceinline__ void cp_wait() {
    asm volatile("cp.async.wait_group %0;" :: "n"(N) : "memory");
}
__device__ __forceinline__ void mma_bf16(float& d0, float& d1, float& d2, float& d3,
                                         unsigned a0, unsigned a1, unsigned a2, unsigned a3,
                                         unsigned b0, unsigned b1) {
    asm volatile(
        "mma.sync.aligned.m16n8k16.row.col.f32.bf16.bf16.f32 "
        "{%0,%1,%2,%3},{%4,%5,%6,%7},{%8,%9},{%0,%1,%2,%3};"
        : "+f"(d0), "+f"(d1), "+f"(d2), "+f"(d3)
        : "r"(a0), "r"(a1), "r"(a2), "r"(a3), "r"(b0), "r"(b1));
}
// MUFU-only gate math (EX2 + RCP.approx; no full-precision DIV)
__device__ __forceinline__ float fsig(float x) {
    float e = __expf(-x);
    return __fdividef(1.f, 1.f + e);
}
__device__ __forceinline__ float ftnh(float x) {
    float e = __expf(2.f * x);             // inf for large x -> tanh -> 1 (safe)
    return 1.f - __fdividef(2.f, e + 1.f);
}
__device__ __forceinline__ float zclamp(float x) { return fminf(fmaxf(x, -30.f), 30.f); }

// ---------------- converts ---------------------------------------------------
__global__ void conv_w(const float* __restrict__ Wx, const float* __restrict__ Wh) {
    int tid = blockIdx.x * blockDim.x + threadIdx.x;
    int stride = gridDim.x * blockDim.x;
    for (int o = tid; o < 2048 * 128; o += stride) {
        int k = o & 127, n = o >> 7;
        g_wxtb[o] = __float2bfloat16(Wx[(size_t)k * 2048 + n]);
    }
    for (int o = tid; o < 2048 * 512; o += stride) {
        int k = o & 511, n = o >> 9;
        g_wht[o] = __float2bfloat16(Wh[(size_t)k * 2048 + n]);
    }
}

__global__ void conv_x(const float* __restrict__ x) {
    const float4* x4 = (const float4*)x;
    size_t N4 = (size_t)512 * 512 * 128 / 4;
    for (size_t o = (size_t)blockIdx.x * blockDim.x + threadIdx.x; o < N4;
         o += (size_t)gridDim.x * blockDim.x) {
        float4 v = x4[o];
        __nv_bfloat162 lo = __floats2bfloat162_rn(v.x, v.y);
        __nv_bfloat162 hi = __floats2bfloat162_rn(v.z, v.w);
        uint2 pk;
        pk.x = *(unsigned*)&lo;
        pk.y = *(unsigned*)&hi;
        *(uint2*)(g_xb + o * 4) = pk;
    }
}

__global__ void reset_k() {
    int tid = blockIdx.x * blockDim.x + threadIdx.x;
    if (tid < 32 * 32) g_barr[tid] = 0u;
    for (int o = tid; o < 512 * 512; o += gridDim.x * blockDim.x)
        g_h[0][o] = __float2bfloat16(0.f);
}

// ---------------- mma helpers (fragment layout proven in rounds 6-7) ---------
__device__ __forceinline__ void h_mma_chunk(const __nv_bfloat16* As, const __nv_bfloat16* Whs,
                                            int kc, int wm, int wn, int tr, int tc,
                                            float acc[2][4][4]) {
#pragma unroll
    for (int k16 = 0; k16 < 8; k16++) {
        unsigned a[2][4];
        int kk = k16 * 16 + tc;
#pragma unroll
        for (int im = 0; im < 2; im++) {
            int r = wm * 32 + im * 16 + tr;
            a[im][0] = *(const unsigned*)(As + r * 136 + kk);
            a[im][1] = *(const unsigned*)(As + (r + 8) * 136 + kk);
            a[im][2] = *(const unsigned*)(As + r * 136 + kk + 8);
            a[im][3] = *(const unsigned*)(As + (r + 8) * 136 + kk + 8);
        }
        int kk2 = kc * 128 + kk;
#pragma unroll
        for (int g = 0; g < 4; g++) {
            int n = g * 16 + wn * 8 + tr;
            unsigned b0 = *(const unsigned*)(Whs + n * 520 + kk2);
            unsigned b1 = *(const unsigned*)(Whs + n * 520 + kk2 + 8);
#pragma unroll
            for (int im = 0; im < 2; im++)
                mma_bf16(acc[im][g][0], acc[im][g][1], acc[im][g][2], acc[im][g][3],
                         a[im][0], a[im][1], a[im][2], a[im][3], b0, b1);
        }
    }
}

__device__ __forceinline__ void x_mma(const __nv_bfloat16* xs, const __nv_bfloat16* Wxs,
                                      int wm, int wn, int tr, int tc,
                                      const float bz[4][2], float acc[2][4][4]) {
#pragma unroll
    for (int im = 0; im < 2; im++)
#pragma unroll
        for (int g = 0; g < 4; g++) {
            acc[im][g][0] = bz[g][0]; acc[im][g][1] = bz[g][1];
            acc[im][g][2] = bz[g][0]; acc[im][g][3] = bz[g][1];
        }
#pragma unroll
    for (int k16 = 0; k16 < 8; k16++) {
        unsigned a[2][4];
        int kk = k16 * 16 + tc;
#pragma unroll
        for (int im = 0; im < 2; im++) {
            int r = wm * 32 + im * 16 + tr;
            a[im][0] = *(const unsigned*)(xs + r * 136 + kk);
            a[im][1] = *(const unsigned*)(xs + (r + 8) * 136 + kk);
            a[im][2] = *(const unsigned*)(xs + r * 136 + kk + 8);
            a[im][3] = *(const unsigned*)(xs + (r + 8) * 136 + kk + 8);
        }
#pragma unroll
        for (int g = 0; g < 4; g++) {
            int n = g * 16 + wn * 8 + tr;
            unsigned b0 = *(const unsigned*)(Wxs + n * 136 + kk);
            unsigned b1 = *(const unsigned*)(Wxs + n * 136 + kk + 8);
#pragma unroll
            for (int im = 0; im < 2; im++)
                mma_bf16(acc[im][g][0], acc[im][g][1], acc[im][g][2], acc[im][g][3],
                         a[im][0], a[im][1], a[im][2], a[im][3], b0, b1);
        }
    }
}

// ---------------- persistent recurrence --------------------------------------
// smem layout (bytes):
//   Whs [64][520] bf16 : 0      .. 66560
//   Wxs [64][136] bf16 : 66560  .. 83968
//   As  3x[128][136] bf16 : 83968 .. 188416   (3 x 34816)
//   xs  [128][136] bf16 : 188416 .. 223232
#define AS_ELEMS (128 * 136)
#define REC_SMEM 223232
__global__ void __launch_bounds__(256, 1) lstm_rec(const float* __restrict__ bias) {
    extern __shared__ char smem[];
    __nv_bfloat16* Whs = (__nv_bfloat16*)smem;
    __nv_bfloat16* Wxs = (__nv_bfloat16*)(smem + 66560);
    __nv_bfloat16* As0 = (__nv_bfloat16*)(smem + 83968);
    __nv_bfloat16* xs  = (__nv_bfloat16*)(smem + 188416);

    const int tid = threadIdx.x;
    const int lane = tid & 31, warp = tid >> 5;
    const int wm = warp & 3, wn = warp >> 2;
    const int q = blockIdx.x & 31, p = blockIdx.x >> 5;
    const int tr = lane >> 2, tc = (lane & 3) * 2;
    const int rbase = p * 128;
    volatile unsigned* barp = (volatile unsigned*)&g_barr[p << 5];

    // ---- prologue ----
    for (int i = tid; i < 4096; i += 256) {
        int rowi = i >> 6, ch = i & 63;
        int gate = rowi >> 4, lc = rowi & 15;
        cp16(&Whs[rowi * 520 + ch * 8],
             g_wht + (size_t)(gate * 512 + q * 16 + lc) * 512 + ch * 8);
    }
    for (int i = tid; i < 1024; i += 256) {
        int rowi = i >> 4, ch = i & 15;
        int gate = rowi >> 4, lc = rowi & 15;
        cp16(&Wxs[rowi * 136 + ch * 8],
             g_wxtb + (size_t)(gate * 512 + q * 16 + lc) * 128 + ch * 8);
    }
    for (int i = tid; i < 2048; i += 256) {
        int r = i >> 4, ch = i & 15;
        cp16(&xs[r * 136 + ch * 8],
             g_xb + ((size_t)(rbase + r) * 512 + 0) * 128 + ch * 8);
    }
    cp_commit(); cp_wait<0>(); __syncthreads();

    float bz[4][2];
    {
        int col = q * 16 + wn * 8 + tc;
#pragma unroll
        for (int g = 0; g < 4; g++) {
            bz[g][0] = bias[g * 512 + col];
            bz[g][1] = bias[g * 512 + col + 1];
        }
    }

    float c[2][4];
#pragma unroll
    for (int im = 0; im < 2; im++)
#pragma unroll
        for (int e = 0; e < 4; e++) c[im][e] = 0.f;

    // acc for step 0: bias + x(0)@Wx
    float acc[2][4][4];
    x_mma(xs, Wxs, wm, wn, tr, tc, bz, acc);
    __syncthreads();   // xs reads complete before step-0 kc2 prefetch overwrites

    for (int t = 0; t < 512; ++t) {
        const int cur = t & 1, nxt = cur ^ 1;
        const __nv_bfloat16* hsrc = g_h[cur];

        // issue h0 -> buf0, h1 -> buf1  (safe: all warps past last buf0/buf1 reads)
#pragma unroll
        for (int cc = 0; cc < 2; cc++) {
            __nv_bfloat16* dst = As0 + cc * AS_ELEMS;
            for (int i = tid; i < 2048; i += 256) {
                int r = i >> 4, ch = i & 15;
                cp16(dst + r * 136 + ch * 8,
                     hsrc + (size_t)(rbase + r) * 512 + cc * 128 + ch * 8);
            }
            cp_commit();
        }
        // pending {h0,h1}

        // kc=0
        cp_wait<1>(); __syncthreads();
        {   // issue h2 -> buf2
            __nv_bfloat16* dst = As0 + 2 * AS_ELEMS;
            for (int i = tid; i < 2048; i += 256) {
                int r = i >> 4, ch = i & 15;
                cp16(dst + r * 136 + ch * 8,
                     hsrc + (size_t)(rbase + r) * 512 + 2 * 128 + ch * 8);
            }
            cp_commit();   // pending {h1,h2}
        }
        h_mma_chunk(As0, Whs, 0, wm, wn, tr, tc, acc);

        // kc=1
        cp_wait<1>(); __syncthreads();
        {   // issue h3 -> buf0 (all warps past kc0 mma via the sync above)
            for (int i = tid; i < 2048; i += 256) {
                int r = i >> 4, ch = i & 15;
                cp16(As0 + r * 136 + ch * 8,
                     hsrc + (size_t)(rbase + r) * 512 + 3 * 128 + ch * 8);
            }
            cp_commit();   // pending {h2,h3}
        }
        h_mma_chunk(As0 + AS_ELEMS, Whs, 1, wm, wn, tr, tc, acc);

        // kc=2
        cp_wait<1>(); __syncthreads();
        if (t < 511) {   // prefetch x(t+1) (xs reads finished in prior shadow)
            for (int i = tid; i < 2048; i += 256) {
                int r = i >> 4, ch = i & 15;
                cp16(&xs[r * 136 + ch * 8],
                     g_xb + ((size_t)(rbase + r) * 512 + (t + 1)) * 128 + ch * 8);
            }
            cp_commit();   // pending {h3,x'}
        }
        h_mma_chunk(As0 + 2 * AS_ELEMS, Whs, 2, wm, wn, tr, tc, acc);

        // kc=3: drain h3 ({h3,x'} if t<511 else {h3})
        if (t < 511) cp_wait<1>(); else cp_wait<0>();
        __syncthreads();
        h_mma_chunk(As0, Whs, 3, wm, wn, tr, tc, acc);

        // ---- gates + state update + h writeback ----
#pragma unroll
        for (int im = 0; im < 2; im++) {
            int grow = rbase + wm * 32 + im * 16 + tr;
            int hcol = q * 16 + wn * 8 + tc;
            float hv[4];
#pragma unroll
            for (int e = 0; e < 4; e++) {
                float gv = ftnh(zclamp(acc[im][0][e]));
                float iv = fsig(zclamp(acc[im][1][e]));
                float fv = fsig(zclamp(acc[im][2][e]));
                float ov = fsig(zclamp(acc[im][3][e]));
                float cc2 = gv * iv + c[im][e] * fv;
                c[im][e] = cc2;
                hv[e] = ftnh(cc2) * ov;
            }
            if (t < 511) {
                *(__nv_bfloat162*)(g_h[nxt] + (size_t)grow * 512 + hcol) =
                    __floats2bfloat162_rn(hv[0], hv[1]);
                *(__nv_bfloat162*)(g_h[nxt] + (size_t)(grow + 8) * 512 + hcol) =
                    __floats2bfloat162_rn(hv[2], hv[3]);
            } else {
                *(float2*)(g_hfinal + (size_t)grow * 512 + hcol) = make_float2(hv[0], hv[1]);
                *(float2*)(g_hfinal + (size_t)(grow + 8) * 512 + hcol) = make_float2(hv[2], hv[3]);
            }
        }

        if (t == 511) break;

        // ---- per-p barrier arrive (32 CTAs per group) ----
        __syncthreads();                  // all h writes issued
        if (tid == 0) {
            __threadfence();              // release
            atomicAdd((unsigned*)barp, 1u);
        }

        // ---- barrier shadow: x-GEMM for t+1 (independent of h(t+1)) ----
        cp_wait<0>();                     // x' load complete
        __syncthreads();
        x_mma(xs, Wxs, wm, wn, tr, tc, bz, acc);

        // ---- poll ----
        if (tid == 0) {
            unsigned target = (unsigned)(t + 1) * 32u;
            while (*barp < target) { }
            __threadfence();              // acquire
        }
        __syncthreads();
    }
}

// ---------------- projection + softmax ---------------------------------------
__global__ void proj_kernel(const float* __restrict__ Wp, const float* __restrict__ bp,
                            float* __restrict__ out) {
    __shared__ float hs[512];
    __shared__ float wred[8];
    int b = blockIdx.x, o = threadIdx.x;
    for (int i = o; i < 512; i += 128)
        hs[i] = fminf(fmaxf(g_hfinal[(size_t)b * 512 + i], -1.f), 1.f);
    __syncthreads();
    float acc = bp[o];
#pragma unroll 8
    for (int k = 0; k < 512; k++) acc = fmaf(hs[k], Wp[(size_t)k * 128 + o], acc);
    float m = acc;
#pragma unroll
    for (int s = 16; s > 0; s >>= 1) m = fmaxf(m, __shfl_xor_sync(0xffffffffu, m, s));
    int w = o >> 5, ln = o & 31;
    if (ln == 0) wred[w] = m;
    __syncthreads();
    m = fmaxf(fmaxf(wred[0], wred[1]), fmaxf(wred[2], wred[3]));
    float e = __expf(acc - m);
    float s = e;
#pragma unroll
    for (int sh = 16; sh > 0; sh >>= 1) s += __shfl_xor_sync(0xffffffffu, s, sh);
    if (ln == 0) wred[4 + w] = s;
    __syncthreads();
    s = wred[4] + wred[5] + wred[6] + wred[7];
    out[(size_t)b * 128 + o] = e * __fdividef(1.f, s);
}

// ---------------- launch ------------------------------------------------------
// Inputs resolved BY ELEMENT COUNT (all six sizes distinct):
//   x: 33554432, Wx: 262144, Wh: 1048576, b: 2048, Wp: 65536, bp: 128
extern "C" void kernel_launch(void* const* d_in, const int* in_sizes, int n_in,
                              void* d_out, int out_size) {
    (void)out_size;
    const float *x = 0, *Wx = 0, *Wh = 0, *b = 0, *Wp = 0, *bp = 0;
    for (int i = 0; i < n_in; i++) {
        switch (in_sizes[i]) {
            case 512 * 512 * 128: x  = (const float*)d_in[i]; break;
            case 128 * 2048:      Wx = (const float*)d_in[i]; break;
            case 512 * 2048:      Wh = (const float*)d_in[i]; break;
            case 2048:            b  = (const float*)d_in[i]; break;
            case 512 * 128:       Wp = (const float*)d_in[i]; break;
            case 128:             bp = (const float*)d_in[i]; break;
            default: break;
        }
    }
    float* out = (float*)d_out;

    cudaFuncSetAttribute(lstm_rec, cudaFuncAttributeMaxDynamicSharedMemorySize, REC_SMEM);

    conv_w<<<512, 256>>>(Wx, Wh);
    conv_x<<<512, 256>>>(x);
    reset_k<<<128, 256>>>();
    lstm_rec<<<NCTA, 256, REC_SMEM>>>(b);
    proj_kernel<<<512, 128>>>(Wp, bp, out);
}

// round 10
// speedup vs baseline: 2.0407x; 1.0214x over previous
#include <cuda_runtime.h>
#include <cuda_bf16.h>
#include <cstdint>
#include <cstddef>

// ---------------------------------------------------------------------------
// LSTM: B=512, T=512, I=128, H=512, O=128. Gates [g,i,f,o].
// Persistent 128 CTAs. CTA (p,q): p = 128-row batch tile (4 groups),
// q = 16 h-cols x 4 gates = 64 N cols. Weights smem-resident.
// Round-10: round-8 skeleton + ldmatrix fragment loads (halves mma-loop
// instruction count; tcgen05 unavailable at the harness's PTX target).
// ---------------------------------------------------------------------------

#define NCTA 128

__device__ __nv_bfloat16  g_wxtb[2048 * 128];            // Wx^T [n][k] bf16
__device__ __nv_bfloat16  g_wht[2048 * 512];             // Wh^T [n][k] bf16
__device__ __nv_bfloat16  g_xb[(size_t)512 * 512 * 128]; // x bf16 [b][t][i]
__device__ __nv_bfloat16  g_h[2][512 * 512];             // ping-pong h
__device__ float          g_hfinal[512 * 512];           // final h fp32
__device__ unsigned       g_barr[32 * 32];               // per-p counters @ [p*32]

// ---------------- PTX helpers ----------------------------------------------
__device__ __forceinline__ unsigned smem_u32(const void* p) {
    return (unsigned)__cvta_generic_to_shared(p);
}
__device__ __forceinline__ void cp16(void* dst_smem, const void* src) {
    asm volatile("cp.async.cg.shared.global [%0], [%1], 16;"
                 :: "r"(smem_u32(dst_smem)), "l"(src) : "memory");
}
__device__ __forceinline__ void cp_commit() {
    asm volatile("cp.async.commit_group;" ::: "memory");
}
template <int N>
__device__ __forceinline__ void cp_wait() {
    asm volatile("cp.async.wait_group %0;" :: "n"(N) : "memory");
}
__device__ __forceinline__ void ldm4(unsigned r[4], unsigned addr) {
    asm volatile("ldmatrix.sync.aligned.m8n8.x4.shared.b16 {%0,%1,%2,%3}, [%4];"
                 : "=r"(r[0]), "=r"(r[1]), "=r"(r[2]), "=r"(r[3]) : "r"(addr));
}
__device__ __forceinline__ void mma_bf16(float& d0, float& d1, float& d2, float& d3,
                                         unsigned a0, unsigned a1, unsigned a2, unsigned a3,
                                         unsigned b0, unsigned b1) {
    asm volatile(
        "mma.sync.aligned.m16n8k16.row.col.f32.bf16.bf16.f32 "
        "{%0,%1,%2,%3},{%4,%5,%6,%7},{%8,%9},{%0,%1,%2,%3};"
        : "+f"(d0), "+f"(d1), "+f"(d2), "+f"(d3)
        : "r"(a0), "r"(a1), "r"(a2), "r"(a3), "r"(b0), "r"(b1));
}
__device__ __forceinline__ float fsig(float x) {
    return __fdividef(1.f, 1.f + __expf(-x));
}
__device__ __forceinline__ float ftnh(float x) {
    return 1.f - __fdividef(2.f, __expf(2.f * x) + 1.f);
}
__device__ __forceinline__ float zclamp(float x) { return fminf(fmaxf(x, -30.f), 30.f); }

// ---- mma block: 8 k16 iterations via ldmatrix ----
// aAddr: per-thread A ldmatrix address (im=0, k16=0); im=1 at +4352 (16 rows x 272B)
// bAddr: per-thread B ldmatrix address (gates {0,1}, k16=0); pairStride to gates {2,3}
__device__ __forceinline__ void mma_block8(unsigned aAddr, unsigned bAddr,
                                           unsigned bPairStride, float acc[2][4][4]) {
#pragma unroll
    for (int k16 = 0; k16 < 8; k16++) {
        unsigned a[2][4], b01[4], b23[4];
        ldm4(a[0], aAddr + k16 * 32);
        ldm4(a[1], aAddr + 4352 + k16 * 32);
        ldm4(b01, bAddr + k16 * 32);
        ldm4(b23, bAddr + bPairStride + k16 * 32);
#pragma unroll
        for (int im = 0; im < 2; im++) {
            mma_bf16(acc[im][0][0], acc[im][0][1], acc[im][0][2], acc[im][0][3],
                     a[im][0], a[im][1], a[im][2], a[im][3], b01[0], b01[1]);
            mma_bf16(acc[im][1][0], acc[im][1][1], acc[im][1][2], acc[im][1][3],
                     a[im][0], a[im][1], a[im][2], a[im][3], b01[2], b01[3]);
            mma_bf16(acc[im][2][0], acc[im][2][1], acc[im][2][2], acc[im][2][3],
                     a[im][0], a[im][1], a[im][2], a[im][3], b23[0], b23[1]);
            mma_bf16(acc[im][3][0], acc[im][3][1], acc[im][3][2], acc[im][3][3],
                     a[im][0], a[im][1], a[im][2], a[im][3], b23[2], b23[3]);
        }
    }
}

// ---------------- converts ---------------------------------------------------
__global__ void conv_w(const float* __restrict__ Wx, const float* __restrict__ Wh) {
    int tid = blockIdx.x * blockDim.x + threadIdx.x;
    int stride = gridDim.x * blockDim.x;
    for (int o = tid; o < 2048 * 128; o += stride) {
        int k = o & 127, n = o >> 7;
        g_wxtb[o] = __float2bfloat16(Wx[(size_t)k * 2048 + n]);
    }
    for (int o = tid; o < 2048 * 512; o += stride) {
        int k = o & 511, n = o >> 9;
        g_wht[o] = __float2bfloat16(Wh[(size_t)k * 2048 + n]);
    }
}

__global__ void conv_x(const float* __restrict__ x) {
    const float4* x4 = (const float4*)x;
    size_t N4 = (size_t)512 * 512 * 128 / 4;
    for (size_t o = (size_t)blockIdx.x * blockDim.x + threadIdx.x; o < N4;
         o += (size_t)gridDim.x * blockDim.x) {
        float4 v = x4[o];
        __nv_bfloat162 lo = __floats2bfloat162_rn(v.x, v.y);
        __nv_bfloat162 hi = __floats2bfloat162_rn(v.z, v.w);
        uint2 pk;
        pk.x = *(unsigned*)&lo;
        pk.y = *(unsigned*)&hi;
        *(uint2*)(g_xb + o * 4) = pk;
    }
}

__global__ void reset_k() {
    int tid = blockIdx.x * blockDim.x + threadIdx.x;
    if (tid < 32 * 32) g_barr[tid] = 0u;
    for (int o = tid; o < 512 * 512; o += gridDim.x * blockDim.x)
        g_h[0][o] = __float2bfloat16(0.f);
}

// ---------------- persistent recurrence --------------------------------------
// smem layout (bytes):
//   Whs [64][520] bf16 : 0      .. 66560
//   Wxs [64][136] bf16 : 66560  .. 83968
//   As  3x[128][136] bf16 : 83968 .. 188416   (3 x 34816)
//   xs  [128][136] bf16 : 188416 .. 223232
#define AS_ELEMS (128 * 136)
#define AS_BYTES 34816
#define REC_SMEM 223232
__global__ void __launch_bounds__(256, 1) lstm_rec(const float* __restrict__ bias) {
    extern __shared__ char smem[];
    __nv_bfloat16* Whs = (__nv_bfloat16*)smem;
    __nv_bfloat16* Wxs = (__nv_bfloat16*)(smem + 66560);
    __nv_bfloat16* As0 = (__nv_bfloat16*)(smem + 83968);
    __nv_bfloat16* xs  = (__nv_bfloat16*)(smem + 188416);

    const int tid = threadIdx.x;
    const int lane = tid & 31, warp = tid >> 5;
    const int wm = warp & 3, wn = warp >> 2;
    const int q = blockIdx.x & 31, p = blockIdx.x >> 5;
    const int tr = lane >> 2, tc = (lane & 3) * 2;
    const int rbase = p * 128;
    volatile unsigned* barp = (volatile unsigned*)&g_barr[p << 5];

    // ---- per-thread ldmatrix addresses ----
    // A (As/xs, row stride 272B): mats = {r..r+7@kk, r+8..15@kk, r..r+7@kk+8, r+8..15@kk+8}
    const unsigned aoff =
        (unsigned)(wm * 32 + (lane & 7) + ((lane >> 3) & 1) * 8) * 272u +
        (unsigned)((lane >> 4) & 1) * 16u;
    // B (row stride Whs=1040B / Wxs=272B): mats = {g0@kk, g0@kk+8, g1@kk, g1@kk+8}
    const unsigned bRowWh =
        (unsigned)(((lane >> 4) & 1) * 16 + wn * 8 + (lane & 7));
    const unsigned bColSel = (unsigned)((lane >> 3) & 1) * 16u;
    const unsigned bWhOff = bRowWh * 1040u + bColSel;
    const unsigned bWxOff = bRowWh * 272u + bColSel;

    const unsigned sWh = smem_u32(Whs) + bWhOff;      // + kc*256 per chunk
    const unsigned sWx = smem_u32(Wxs) + bWxOff;
    const unsigned sX  = smem_u32(xs) + aoff;
    unsigned sA[3];
    sA[0] = smem_u32(As0) + aoff;
    sA[1] = sA[0] + AS_BYTES;
    sA[2] = sA[0] + 2 * AS_BYTES;
    const unsigned WH_PAIR = 32u * 1040u;   // gates {0,1} -> {2,3}
    const unsigned WX_PAIR = 32u * 272u;

    // ---- prologue ----
    for (int i = tid; i < 4096; i += 256) {
        int rowi = i >> 6, ch = i & 63;
        int gate = rowi >> 4, lc = rowi & 15;
        cp16(&Whs[rowi * 520 + ch * 8],
             g_wht + (size_t)(gate * 512 + q * 16 + lc) * 512 + ch * 8);
    }
    for (int i = tid; i < 1024; i += 256) {
        int rowi = i >> 4, ch = i & 15;
        int gate = rowi >> 4, lc = rowi & 15;
        cp16(&Wxs[rowi * 136 + ch * 8],
             g_wxtb + (size_t)(gate * 512 + q * 16 + lc) * 128 + ch * 8);
    }
    for (int i = tid; i < 2048; i += 256) {
        int r = i >> 4, ch = i & 15;
        cp16(&xs[r * 136 + ch * 8],
             g_xb + ((size_t)(rbase + r) * 512 + 0) * 128 + ch * 8);
    }
    cp_commit(); cp_wait<0>(); __syncthreads();

    float bz[4][2];
    {
        int col = q * 16 + wn * 8 + tc;
#pragma unroll
        for (int g = 0; g < 4; g++) {
            bz[g][0] = bias[g * 512 + col];
            bz[g][1] = bias[g * 512 + col + 1];
        }
    }

    float c[2][4];
#pragma unroll
    for (int im = 0; im < 2; im++)
#pragma unroll
        for (int e = 0; e < 4; e++) c[im][e] = 0.f;

    // acc for step 0: bias + x(0)@Wx
    float acc[2][4][4];
#pragma unroll
    for (int im = 0; im < 2; im++)
#pragma unroll
        for (int g = 0; g < 4; g++) {
            acc[im][g][0] = bz[g][0]; acc[im][g][1] = bz[g][1];
            acc[im][g][2] = bz[g][0]; acc[im][g][3] = bz[g][1];
        }
    mma_block8(sX, sWx, WX_PAIR, acc);
    __syncthreads();   // xs reads complete before step-0 kc2 prefetch overwrites

    for (int t = 0; t < 512; ++t) {
        const int cur = t & 1, nxt = cur ^ 1;
        const __nv_bfloat16* hsrc = g_h[cur];

        // issue h0 -> buf0, h1 -> buf1
#pragma unroll
        for (int cc = 0; cc < 2; cc++) {
            __nv_bfloat16* dst = As0 + cc * AS_ELEMS;
            for (int i = tid; i < 2048; i += 256) {
                int r = i >> 4, ch = i & 15;
                cp16(dst + r * 136 + ch * 8,
                     hsrc + (size_t)(rbase + r) * 512 + cc * 128 + ch * 8);
            }
            cp_commit();
        }
        // pending {h0,h1}

        // kc=0
        cp_wait<1>(); __syncthreads();
        {   // issue h2 -> buf2
            __nv_bfloat16* dst = As0 + 2 * AS_ELEMS;
            for (int i = tid; i < 2048; i += 256) {
                int r = i >> 4, ch = i & 15;
                cp16(dst + r * 136 + ch * 8,
                     hsrc + (size_t)(rbase + r) * 512 + 2 * 128 + ch * 8);
            }
            cp_commit();   // pending {h1,h2}
        }
        mma_block8(sA[0], sWh + 0 * 256, WH_PAIR, acc);

        // kc=1
        cp_wait<1>(); __syncthreads();
        {   // issue h3 -> buf0
            for (int i = tid; i < 2048; i += 256) {
                int r = i >> 4, ch = i & 15;
                cp16(As0 + r * 136 + ch * 8,
                     hsrc + (size_t)(rbase + r) * 512 + 3 * 128 + ch * 8);
            }
            cp_commit();   // pending {h2,h3}
        }
        mma_block8(sA[1], sWh + 1 * 256, WH_PAIR, acc);

        // kc=2
        cp_wait<1>(); __syncthreads();
        if (t < 511) {   // prefetch x(t+1)
            for (int i = tid; i < 2048; i += 256) {
                int r = i >> 4, ch = i & 15;
                cp16(&xs[r * 136 + ch * 8],
                     g_xb + ((size_t)(rbase + r) * 512 + (t + 1)) * 128 + ch * 8);
            }
            cp_commit();   // pending {h3,x'}
        }
        mma_block8(sA[2], sWh + 2 * 256, WH_PAIR, acc);

        // kc=3
        if (t < 511) cp_wait<1>(); else cp_wait<0>();
        __syncthreads();
        mma_block8(sA[0], sWh + 3 * 256, WH_PAIR, acc);

        // ---- gates + state update + h writeback ----
#pragma unroll
        for (int im = 0; im < 2; im++) {
            int grow = rbase + wm * 32 + im * 16 + tr;
            int hcol = q * 16 + wn * 8 + tc;
            float hv[4];
#pragma unroll
            for (int e = 0; e < 4; e++) {
                float gv = ftnh(zclamp(acc[im][0][e]));
                float iv = fsig(zclamp(acc[im][1][e]));
                float fv = fsig(zclamp(acc[im][2][e]));
                float ov = fsig(zclamp(acc[im][3][e]));
                float cc2 = gv * iv + c[im][e] * fv;
                c[im][e] = cc2;
                hv[e] = ftnh(cc2) * ov;
            }
            if (t < 511) {
                *(__nv_bfloat162*)(g_h[nxt] + (size_t)grow * 512 + hcol) =
                    __floats2bfloat162_rn(hv[0], hv[1]);
                *(__nv_bfloat162*)(g_h[nxt] + (size_t)(grow + 8) * 512 + hcol) =
                    __floats2bfloat162_rn(hv[2], hv[3]);
            } else {
                *(float2*)(g_hfinal + (size_t)grow * 512 + hcol) = make_float2(hv[0], hv[1]);
                *(float2*)(g_hfinal + (size_t)(grow + 8) * 512 + hcol) = make_float2(hv[2], hv[3]);
            }
        }

        if (t == 511) break;

        // ---- per-p barrier arrive ----
        __syncthreads();
        if (tid == 0) {
            __threadfence();
            atomicAdd((unsigned*)barp, 1u);
        }

        // ---- barrier shadow: x-GEMM for t+1 ----
        cp_wait<0>();
        __syncthreads();
#pragma unroll
        for (int im = 0; im < 2; im++)
#pragma unroll
            for (int g = 0; g < 4; g++) {
                acc[im][g][0] = bz[g][0]; acc[im][g][1] = bz[g][1];
                acc[im][g][2] = bz[g][0]; acc[im][g][3] = bz[g][1];
            }
        mma_block8(sX, sWx, WX_PAIR, acc);

        // ---- poll ----
        if (tid == 0) {
            unsigned target = (unsigned)(t + 1) * 32u;
            while (*barp < target) { }
            __threadfence();
        }
        __syncthreads();
    }
}

// ---------------- projection + softmax ---------------------------------------
__global__ void proj_kernel(const float* __restrict__ Wp, const float* __restrict__ bp,
                            float* __restrict__ out) {
    __shared__ float hs[512];
    __shared__ float wred[8];
    int b = blockIdx.x, o = threadIdx.x;
    for (int i = o; i < 512; i += 128)
        hs[i] = fminf(fmaxf(g_hfinal[(size_t)b * 512 + i], -1.f), 1.f);
    __syncthreads();
    float acc = bp[o];
#pragma unroll 8
    for (int k = 0; k < 512; k++) acc = fmaf(hs[k], Wp[(size_t)k * 128 + o], acc);
    float m = acc;
#pragma unroll
    for (int s = 16; s > 0; s >>= 1) m = fmaxf(m, __shfl_xor_sync(0xffffffffu, m, s));
    int w = o >> 5, ln = o & 31;
    if (ln == 0) wred[w] = m;
    __syncthreads();
    m = fmaxf(fmaxf(wred[0], wred[1]), fmaxf(wred[2], wred[3]));
    float e = __expf(acc - m);
    float s = e;
#pragma unroll
    for (int sh = 16; sh > 0; sh >>= 1) s += __shfl_xor_sync(0xffffffffu, s, sh);
    if (ln == 0) wred[4 + w] = s;
    __syncthreads();
    s = wred[4] + wred[5] + wred[6] + wred[7];
    out[(size_t)b * 128 + o] = e * __fdividef(1.f, s);
}

// ---------------- launch ------------------------------------------------------
// Inputs resolved BY ELEMENT COUNT (all six sizes distinct):
//   x: 33554432, Wx: 262144, Wh: 1048576, b: 2048, Wp: 65536, bp: 128
extern "C" void kernel_launch(void* const* d_in, const int* in_sizes, int n_in,
                              void* d_out, int out_size) {
    (void)out_size;
    const float *x = 0, *Wx = 0, *Wh = 0, *b = 0, *Wp = 0, *bp = 0;
    for (int i = 0; i < n_in; i++) {
        switch (in_sizes[i]) {
            case 512 * 512 * 128: x  = (const float*)d_in[i]; break;
            case 128 * 2048:      Wx = (const float*)d_in[i]; break;
            case 512 * 2048:      Wh = (const float*)d_in[i]; break;
            case 2048:            b  = (const float*)d_in[i]; break;
            case 512 * 128:       Wp = (const float*)d_in[i]; break;
            case 128:             bp = (const float*)d_in[i]; break;
            default: break;
        }
    }
    float* out = (float*)d_out;

    cudaFuncSetAttribute(lstm_rec, cudaFuncAttributeMaxDynamicSharedMemorySize, REC_SMEM);

    conv_w<<<512, 256>>>(Wx, Wh);
    conv_x<<<512, 256>>>(x);
    reset_k<<<128, 256>>>();
    lstm_rec<<<NCTA, 256, REC_SMEM>>>(b);
    proj_kernel<<<512, 128>>>(Wp, bp, out);
}

// round 11
// speedup vs baseline: 2.3418x; 1.1476x over previous
#include <cuda_runtime.h>
#include <cuda_bf16.h>
#include <cstdint>
#include <cstddef>

// ---------------------------------------------------------------------------
// LSTM: B=512, T=512, I=128, H=512, O=128. Gates [g,i,f,o].
// Persistent 128 CTAs. CTA (p,q): p = 128-row batch tile (4 groups),
// q = 16 h-cols x 4 gates = 64 N cols. Weights smem-resident.
// Round-11: warp-decoupled steady loop (no CTA __syncthreads), pair-local
// named barriers, warp-granular inter-CTA barrier, MUFU.TANH gates.
// ---------------------------------------------------------------------------

#define NCTA 128

__device__ __nv_bfloat16  g_wxtb[2048 * 128];            // Wx^T [n][k] bf16
__device__ __nv_bfloat16  g_wht[2048 * 512];             // Wh^T [n][k] bf16
__device__ __nv_bfloat16  g_xb[(size_t)512 * 512 * 128]; // x bf16 [b][t][i]
__device__ __nv_bfloat16  g_h[2][512 * 512];             // ping-pong h
__device__ float          g_hfinal[512 * 512];           // final h fp32
__device__ unsigned       g_barr[32 * 32];               // per-p counters @ [p*32]

// ---------------- PTX helpers ----------------------------------------------
__device__ __forceinline__ unsigned smem_u32(const void* p) {
    return (unsigned)__cvta_generic_to_shared(p);
}
__device__ __forceinline__ void cp16(void* dst_smem, const void* src) {
    asm volatile("cp.async.cg.shared.global [%0], [%1], 16;"
                 :: "r"(smem_u32(dst_smem)), "l"(src) : "memory");
}
__device__ __forceinline__ void cp_commit() {
    asm volatile("cp.async.commit_group;" ::: "memory");
}
template <int N>
__device__ __forceinline__ void cp_wait() {
    asm volatile("cp.async.wait_group %0;" :: "n"(N) : "memory");
}
__device__ __forceinline__ void ldm4(unsigned r[4], unsigned addr) {
    asm volatile("ldmatrix.sync.aligned.m8n8.x4.shared.b16 {%0,%1,%2,%3}, [%4];"
                 : "=r"(r[0]), "=r"(r[1]), "=r"(r[2]), "=r"(r[3]) : "r"(addr));
}
__device__ __forceinline__ void mma_bf16(float& d0, float& d1, float& d2, float& d3,
                                         unsigned a0, unsigned a1, unsigned a2, unsigned a3,
                                         unsigned b0, unsigned b1) {
    asm volatile(
        "mma.sync.aligned.m16n8k16.row.col.f32.bf16.bf16.f32 "
        "{%0,%1,%2,%3},{%4,%5,%6,%7},{%8,%9},{%0,%1,%2,%3};"
        : "+f"(d0), "+f"(d1), "+f"(d2), "+f"(d3)
        : "r"(a0), "r"(a1), "r"(a2), "r"(a3), "r"(b0), "r"(b1));
}
// MUFU.TANH gates (single-op, short dependency chain)
__device__ __forceinline__ float tanhfast(float x) {
    float y;
    asm("tanh.approx.f32 %0, %1;" : "=f"(y) : "f"(x));
    return y;
}
__device__ __forceinline__ float fsig(float x) {
    return fmaf(0.5f, tanhfast(0.5f * x), 0.5f);
}

// pair-local named barrier: warps (wm,0) and (wm,1), 64 threads, id = wm+1
__device__ __forceinline__ void barpair(int wm) {
    asm volatile("bar.sync %0, 64;" :: "r"(wm + 1) : "memory");
}

// ---- mma block: 8 k16 iterations via ldmatrix (layout proven round 10) ----
__device__ __forceinline__ void mma_block8(unsigned aAddr, unsigned bAddr,
                                           unsigned bPairStride, float acc[2][4][4]) {
#pragma unroll
    for (int k16 = 0; k16 < 8; k16++) {
        unsigned a[2][4], b01[4], b23[4];
        ldm4(a[0], aAddr + k16 * 32);
        ldm4(a[1], aAddr + 4352 + k16 * 32);
        ldm4(b01, bAddr + k16 * 32);
        ldm4(b23, bAddr + bPairStride + k16 * 32);
#pragma unroll
        for (int im = 0; im < 2; im++) {
            mma_bf16(acc[im][0][0], acc[im][0][1], acc[im][0][2], acc[im][0][3],
                     a[im][0], a[im][1], a[im][2], a[im][3], b01[0], b01[1]);
            mma_bf16(acc[im][1][0], acc[im][1][1], acc[im][1][2], acc[im][1][3],
                     a[im][0], a[im][1], a[im][2], a[im][3], b01[2], b01[3]);
            mma_bf16(acc[im][2][0], acc[im][2][1], acc[im][2][2], acc[im][2][3],
                     a[im][0], a[im][1], a[im][2], a[im][3], b23[0], b23[1]);
            mma_bf16(acc[im][3][0], acc[im][3][1], acc[im][3][2], acc[im][3][3],
                     a[im][0], a[im][1], a[im][2], a[im][3], b23[2], b23[3]);
        }
    }
}

// ---------------- converts ---------------------------------------------------
__global__ void conv_w(const float* __restrict__ Wx, const float* __restrict__ Wh) {
    int tid = blockIdx.x * blockDim.x + threadIdx.x;
    int stride = gridDim.x * blockDim.x;
    for (int o = tid; o < 2048 * 128; o += stride) {
        int k = o & 127, n = o >> 7;
        g_wxtb[o] = __float2bfloat16(Wx[(size_t)k * 2048 + n]);
    }
    for (int o = tid; o < 2048 * 512; o += stride) {
        int k = o & 511, n = o >> 9;
        g_wht[o] = __float2bfloat16(Wh[(size_t)k * 2048 + n]);
    }
}

__global__ void conv_x(const float* __restrict__ x) {
    const float4* x4 = (const float4*)x;
    size_t N4 = (size_t)512 * 512 * 128 / 4;
    for (size_t o = (size_t)blockIdx.x * blockDim.x + threadIdx.x; o < N4;
         o += (size_t)gridDim.x * blockDim.x) {
        float4 v = x4[o];
        __nv_bfloat162 lo = __floats2bfloat162_rn(v.x, v.y);
        __nv_bfloat162 hi = __floats2bfloat162_rn(v.z, v.w);
        uint2 pk;
        pk.x = *(unsigned*)&lo;
        pk.y = *(unsigned*)&hi;
        *(uint2*)(g_xb + o * 4) = pk;
    }
}

__global__ void reset_k() {
    int tid = blockIdx.x * blockDim.x + threadIdx.x;
    if (tid < 32 * 32) g_barr[tid] = 0u;
    for (int o = tid; o < 512 * 512; o += gridDim.x * blockDim.x)
        g_h[0][o] = __float2bfloat16(0.f);
}

// ---------------- persistent recurrence --------------------------------------
// smem layout (bytes):
//   Whs [64][520] bf16 : 0      .. 66560
//   Wxs [64][136] bf16 : 66560  .. 83968
//   As  3x[128][136] bf16 : 83968 .. 188416   (3 x 34816)
//   xs  [128][136] bf16 : 188416 .. 223232
#define AS_ELEMS (128 * 136)
#define AS_BYTES 34816
#define REC_SMEM 223232
__global__ void __launch_bounds__(256, 1) lstm_rec(const float* __restrict__ bias) {
    extern __shared__ char smem[];
    __nv_bfloat16* Whs = (__nv_bfloat16*)smem;
    __nv_bfloat16* Wxs = (__nv_bfloat16*)(smem + 66560);
    __nv_bfloat16* As0 = (__nv_bfloat16*)(smem + 83968);
    __nv_bfloat16* xs  = (__nv_bfloat16*)(smem + 188416);

    const int tid = threadIdx.x;
    const int lane = tid & 31, warp = tid >> 5;
    const int wm = warp & 3, wn = warp >> 2;
    const int q = blockIdx.x & 31, p = blockIdx.x >> 5;
    const int tr = lane >> 2, tc = (lane & 3) * 2;
    const int rbase = p * 128;
    const int pairrow = wm * 32 + wn * 16;   // this warp's 16-row staging slice
    volatile unsigned* barp = (volatile unsigned*)&g_barr[p << 5];

    // ---- per-thread ldmatrix addresses (verified in round 10) ----
    const unsigned aoff =
        (unsigned)(wm * 32 + (lane & 7) + ((lane >> 3) & 1) * 8) * 272u +
        (unsigned)((lane >> 4) & 1) * 16u;
    const unsigned bRowWh =
        (unsigned)(((lane >> 4) & 1) * 16 + wn * 8 + (lane & 7));
    const unsigned bColSel = (unsigned)((lane >> 3) & 1) * 16u;
    const unsigned sWh = smem_u32(Whs) + bRowWh * 1040u + bColSel;   // + kc*256
    const unsigned sWx = smem_u32(Wxs) + bRowWh * 272u + bColSel;
    const unsigned sX  = smem_u32(xs) + aoff;
    unsigned sA[3];
    sA[0] = smem_u32(As0) + aoff;
    sA[1] = sA[0] + AS_BYTES;
    sA[2] = sA[0] + 2 * AS_BYTES;
    const unsigned WH_PAIR = 32u * 1040u;
    const unsigned WX_PAIR = 32u * 272u;

    // ---- prologue (CTA-wide, syncthreads allowed here) ----
    for (int i = tid; i < 4096; i += 256) {
        int rowi = i >> 6, ch = i & 63;
        int gate = rowi >> 4, lc = rowi & 15;
        cp16(&Whs[rowi * 520 + ch * 8],
             g_wht + (size_t)(gate * 512 + q * 16 + lc) * 512 + ch * 8);
    }
    for (int i = tid; i < 1024; i += 256) {
        int rowi = i >> 4, ch = i & 15;
        int gate = rowi >> 4, lc = rowi & 15;
        cp16(&Wxs[rowi * 136 + ch * 8],
             g_wxtb + (size_t)(gate * 512 + q * 16 + lc) * 128 + ch * 8);
    }
    for (int i = tid; i < 2048; i += 256) {
        int r = i >> 4, ch = i & 15;
        cp16(&xs[r * 136 + ch * 8],
             g_xb + ((size_t)(rbase + r) * 512 + 0) * 128 + ch * 8);
    }
    cp_commit(); cp_wait<0>(); __syncthreads();

    float bz[4][2];
    {
        int col = q * 16 + wn * 8 + tc;
#pragma unroll
        for (int g = 0; g < 4; g++) {
            bz[g][0] = bias[g * 512 + col];
            bz[g][1] = bias[g * 512 + col + 1];
        }
    }

    float c[2][4];
#pragma unroll
    for (int im = 0; im < 2; im++)
#pragma unroll
        for (int e = 0; e < 4; e++) c[im][e] = 0.f;

    // acc for step 0: bias + x(0)@Wx
    float acc[2][4][4];
#pragma unroll
    for (int im = 0; im < 2; im++)
#pragma unroll
        for (int g = 0; g < 4; g++) {
            acc[im][g][0] = bz[g][0]; acc[im][g][1] = bz[g][1];
            acc[im][g][2] = bz[g][0]; acc[im][g][3] = bz[g][1];
        }
    mma_block8(sX, sWx, WX_PAIR, acc);
    __syncthreads();   // last CTA-wide sync; steady loop is warp/pair-local

    for (int t = 0; t < 512; ++t) {
        const int cur = t & 1, nxt = cur ^ 1;
        const __nv_bfloat16* hsrc = g_h[cur] + (size_t)(rbase + pairrow) * 512;

        // stage this warp's 16-row slice of h chunks 0,1 (two groups)
#pragma unroll
        for (int cc = 0; cc < 2; cc++) {
            __nv_bfloat16* buf = As0 + cc * AS_ELEMS;
            for (int i = lane; i < 256; i += 32) {
                int r = i >> 4, ch = i & 15;
                cp16(buf + (pairrow + r) * 136 + ch * 8,
                     hsrc + (size_t)r * 512 + cc * 128 + ch * 8);
            }
            cp_commit();
        }
        // pending {h0,h1}

        // kc=0: h0 ready; stage h2 -> buf2
        cp_wait<1>(); barpair(wm);
        for (int i = lane; i < 256; i += 32) {
            int r = i >> 4, ch = i & 15;
            cp16(As0 + 2 * AS_ELEMS + (pairrow + r) * 136 + ch * 8,
                 hsrc + (size_t)r * 512 + 2 * 128 + ch * 8);
        }
        cp_commit();   // {h1,h2}
        mma_block8(sA[0], sWh, WH_PAIR, acc);

        // kc=1: h1 ready; stage h3 -> buf0 (pair done with buf0 via barpair)
        cp_wait<1>(); barpair(wm);
        for (int i = lane; i < 256; i += 32) {
            int r = i >> 4, ch = i & 15;
            cp16(As0 + (pairrow + r) * 136 + ch * 8,
                 hsrc + (size_t)r * 512 + 3 * 128 + ch * 8);
        }
        cp_commit();   // {h2,h3}
        mma_block8(sA[1], sWh + 256, WH_PAIR, acc);

        // kc=2: h2 ready; prefetch x(t+1) slice
        cp_wait<1>(); barpair(wm);
        if (t < 511) {
            for (int i = lane; i < 256; i += 32) {
                int r = i >> 4, ch = i & 15;
                cp16(xs + (pairrow + r) * 136 + ch * 8,
                     g_xb + ((size_t)(rbase + pairrow + r) * 512 + (t + 1)) * 128 + ch * 8);
            }
            cp_commit();   // {h3,x'}
        }
        mma_block8(sA[2], sWh + 512, WH_PAIR, acc);

        // kc=3: h3 ready
        if (t < 511) cp_wait<1>(); else cp_wait<0>();
        barpair(wm);
        mma_block8(sA[0], sWh + 768, WH_PAIR, acc);

        // ---- gates + state update + h writeback (MUFU.TANH) ----
#pragma unroll
        for (int im = 0; im < 2; im++) {
            int grow = rbase + wm * 32 + im * 16 + tr;
            int hcol = q * 16 + wn * 8 + tc;
            float hv[4];
#pragma unroll
            for (int e = 0; e < 4; e++) {
                float gv = tanhfast(acc[im][0][e]);
                float iv = fsig(acc[im][1][e]);
                float fv = fsig(acc[im][2][e]);
                float ov = fsig(acc[im][3][e]);
                float cc2 = gv * iv + c[im][e] * fv;
                c[im][e] = cc2;
                hv[e] = tanhfast(cc2) * ov;
            }
            if (t < 511) {
                *(__nv_bfloat162*)(g_h[nxt] + (size_t)grow * 512 + hcol) =
                    __floats2bfloat162_rn(hv[0], hv[1]);
                *(__nv_bfloat162*)(g_h[nxt] + (size_t)(grow + 8) * 512 + hcol) =
                    __floats2bfloat162_rn(hv[2], hv[3]);
            } else {
                *(float2*)(g_hfinal + (size_t)grow * 512 + hcol) = make_float2(hv[0], hv[1]);
                *(float2*)(g_hfinal + (size_t)(grow + 8) * 512 + hcol) = make_float2(hv[2], hv[3]);
            }
        }

        if (t == 511) break;

        // ---- warp-granular inter-CTA barrier arrive (target: 256 warps/group) ----
        __syncwarp();
        if (lane == 0) {
            __threadfence();
            atomicAdd((unsigned*)barp, 1u);
        }

        // ---- barrier shadow: x-GEMM for t+1 ----
        cp_wait<0>();      // x' slice complete (this thread's FIFO drained)
        barpair(wm);       // sibling's x' slice visible too
#pragma unroll
        for (int im = 0; im < 2; im++)
#pragma unroll
            for (int g = 0; g < 4; g++) {
                acc[im][g][0] = bz[g][0]; acc[im][g][1] = bz[g][1];
                acc[im][g][2] = bz[g][0]; acc[im][g][3] = bz[g][1];
            }
        mma_block8(sX, sWx, WX_PAIR, acc);

        // ---- poll (all lanes; coalesces to one request per warp) ----
        {
            unsigned target = (unsigned)(t + 1) * 256u;
            while (*barp < target) { }
            __threadfence();
        }
    }
}

// ---------------- projection + softmax ---------------------------------------
__global__ void proj_kernel(const float* __restrict__ Wp, const float* __restrict__ bp,
                            float* __restrict__ out) {
    __shared__ float hs[512];
    __shared__ float wred[8];
    int b = blockIdx.x, o = threadIdx.x;
    for (int i = o; i < 512; i += 128)
        hs[i] = fminf(fmaxf(g_hfinal[(size_t)b * 512 + i], -1.f), 1.f);
    __syncthreads();
    float acc = bp[o];
#pragma unroll 8
    for (int k = 0; k < 512; k++) acc = fmaf(hs[k], Wp[(size_t)k * 128 + o], acc);
    float m = acc;
#pragma unroll
    for (int s = 16; s > 0; s >>= 1) m = fmaxf(m, __shfl_xor_sync(0xffffffffu, m, s));
    int w = o >> 5, ln = o & 31;
    if (ln == 0) wred[w] = m;
    __syncthreads();
    m = fmaxf(fmaxf(wred[0], wred[1]), fmaxf(wred[2], wred[3]));
    float e = __expf(acc - m);
    float s = e;
#pragma unroll
    for (int sh = 16; sh > 0; sh >>= 1) s += __shfl_xor_sync(0xffffffffu, s, sh);
    if (ln == 0) wred[4 + w] = s;
    __syncthreads();
    s = wred[4] + wred[5] + wred[6] + wred[7];
    out[(size_t)b * 128 + o] = e * __fdividef(1.f, s);
}

// ---------------- launch ------------------------------------------------------
// Inputs resolved BY ELEMENT COUNT (all six sizes distinct):
//   x: 33554432, Wx: 262144, Wh: 1048576, b: 2048, Wp: 65536, bp: 128
extern "C" void kernel_launch(void* const* d_in, const int* in_sizes, int n_in,
                              void* d_out, int out_size) {
    (void)out_size;
    const float *x = 0, *Wx = 0, *Wh = 0, *b = 0, *Wp = 0, *bp = 0;
    for (int i = 0; i < n_in; i++) {
        switch (in_sizes[i]) {
            case 512 * 512 * 128: x  = (const float*)d_in[i]; break;
            case 128 * 2048:      Wx = (const float*)d_in[i]; break;
            case 512 * 2048:      Wh = (const float*)d_in[i]; break;
            case 2048:            b  = (const float*)d_in[i]; break;
            case 512 * 128:       Wp = (const float*)d_in[i]; break;
            case 128:             bp = (const float*)d_in[i]; break;
            default: break;
        }
    }
    float* out = (float*)d_out;

    cudaFuncSetAttribute(lstm_rec, cudaFuncAttributeMaxDynamicSharedMemorySize, REC_SMEM);

    conv_w<<<512, 256>>>(Wx, Wh);
    conv_x<<<512, 256>>>(x);
    reset_k<<<128, 256>>>();
    lstm_rec<<<NCTA, 256, REC_SMEM>>>(b);
    proj_kernel<<<512, 128>>>(Wp, bp, out);
}